// round 1
// baseline (speedup 1.0000x reference)
#include <cuda_runtime.h>

#define HW   4096
#define NC   128
#define CR   32
#define KK   49

// scratch for generated per-pixel kernels: [B=4][49][64*64]
__device__ float g_kernel[4 * KK * HW];

// ---------------------------------------------------------------------------
// Kernel 1: generate involution kernels.
// f = relu(BN(w1 @ x + b1)); k = w2 @ f + b2   -> g_kernel[b, t, h, w]
// 1 pixel per thread. 128 blocks x 128 threads.
// ---------------------------------------------------------------------------
__global__ __launch_bounds__(128) void gen_kernel(
    const float* __restrict__ x,  const float* __restrict__ w1,
    const float* __restrict__ b1, const float* __restrict__ gamma,
    const float* __restrict__ beta, const float* __restrict__ mean,
    const float* __restrict__ var,  const float* __restrict__ w2,
    const float* __restrict__ b2)
{
    __shared__ __align__(16) float w1t[NC * CR];   // [c][o]
    __shared__ __align__(16) float w2t[CR * 52];   // [o][t], padded 49->52
    __shared__ float s_scale[CR], s_shift[CR];

    const int tid = threadIdx.x;

    // transpose w1 [o][c] -> [c][o]
    for (int i = tid; i < NC * CR; i += 128) {
        int o = i >> 7, c = i & 127;
        w1t[c * CR + o] = w1[i];
    }
    // transpose w2 [t][o] -> [o][t] (+ zero pads t=49..51)
    for (int i = tid; i < KK * CR; i += 128) {
        int t = i >> 5, o = i & 31;
        w2t[o * 52 + t] = w2[i];
    }
    if (tid < 96) {
        int o = tid & 31, p = tid >> 5;     // p in 0..2
        w2t[o * 52 + 49 + p] = 0.f;
    }
    if (tid < CR) {
        float sc = gamma[tid] * rsqrtf(var[tid] + 1e-5f);
        s_scale[tid] = sc;
        s_shift[tid] = beta[tid] - mean[tid] * sc;
    }
    __syncthreads();

    const int pixel = blockIdx.x * 128 + tid;   // 0..16383
    const int b  = pixel >> 12;
    const int hw = pixel & (HW - 1);

    float f[CR];
    #pragma unroll
    for (int o = 0; o < CR; o++) f[o] = b1[o];

    const float* xp = x + (size_t)b * NC * HW + hw;
    #pragma unroll 4
    for (int c = 0; c < NC; c++) {
        float xv = xp[(size_t)c * HW];
        const float4* wrow = (const float4*)&w1t[c * CR];
        #pragma unroll
        for (int o4 = 0; o4 < 8; o4++) {
            float4 w = wrow[o4];
            f[o4 * 4 + 0] = fmaf(w.x, xv, f[o4 * 4 + 0]);
            f[o4 * 4 + 1] = fmaf(w.y, xv, f[o4 * 4 + 1]);
            f[o4 * 4 + 2] = fmaf(w.z, xv, f[o4 * 4 + 2]);
            f[o4 * 4 + 3] = fmaf(w.w, xv, f[o4 * 4 + 3]);
        }
    }
    #pragma unroll
    for (int o = 0; o < CR; o++) {
        float v = fmaf(f[o], s_scale[o], s_shift[o]);
        f[o] = v > 0.f ? v : 0.f;
    }

    float kacc[52];
    #pragma unroll
    for (int t = 0; t < 52; t++) kacc[t] = (t < KK) ? b2[t] : 0.f;

    #pragma unroll
    for (int o = 0; o < CR; o++) {
        float fo = f[o];
        const float4* wrow = (const float4*)&w2t[o * 52];
        #pragma unroll
        for (int t4 = 0; t4 < 13; t4++) {
            float4 w = wrow[t4];
            kacc[t4 * 4 + 0] = fmaf(w.x, fo, kacc[t4 * 4 + 0]);
            kacc[t4 * 4 + 1] = fmaf(w.y, fo, kacc[t4 * 4 + 1]);
            kacc[t4 * 4 + 2] = fmaf(w.z, fo, kacc[t4 * 4 + 2]);
            kacc[t4 * 4 + 3] = fmaf(w.w, fo, kacc[t4 * 4 + 3]);
        }
    }

    float* kp = g_kernel + (size_t)b * KK * HW + hw;
    #pragma unroll
    for (int t = 0; t < KK; t++) kp[(size_t)t * HW] = kacc[t];
}

// ---------------------------------------------------------------------------
// Kernel 2: involution accumulation.
// out[b,c,h,w] = sum_{i,j} g_kernel[b, i*7+j, h, w] * x[b, c, h+i-3, w+j-3]
// Block = (b, 8-row tile, 32-channel group). 256 threads:
//   warp = one full 64-wide output row, thread = 2 adjacent pixels.
// Per-pixel kernel weights (49 x float2) held in registers, reused over all
// 32 channels. x halo staged in shared (8-channel chunks, padded stride 72).
// All shared loads are lane-consecutive LDS.64 -> conflict free.
// ---------------------------------------------------------------------------
__global__ __launch_bounds__(256) void inv_kernel(
    const float* __restrict__ x, float* __restrict__ out)
{
    __shared__ __align__(16) float xs[8 * 14 * 72];   // 32256 B

    const int bx = blockIdx.x;          // 0..127
    const int b  = bx >> 5;
    const int ht = (bx >> 2) & 7;
    const int cg = bx & 3;
    const int h0 = ht * 8;
    const int cbase = cg * 32;

    const int tid  = threadIdx.x;
    const int hloc = tid >> 5;          // 0..7 output row
    const int lane = tid & 31;
    const int wloc = lane * 2;          // 0,2,...,62

    // preload this thread's 49 kernel weights for its 2 pixels
    float2 kv[KK];
    {
        const float* kp = g_kernel + (size_t)b * KK * HW + (h0 + hloc) * 64 + wloc;
        #pragma unroll
        for (int t = 0; t < KK; t++)
            kv[t] = *(const float2*)(kp + (size_t)t * HW);
    }

    const size_t out_pix = (size_t)(h0 + hloc) * 64 + wloc;

    for (int chunk = 0; chunk < 4; chunk++) {
        const int c0 = cbase + chunk * 8;
        __syncthreads();   // previous chunk fully consumed
        // load halo for 8 channels: rows h0-3..h0+10, cols -3..68 (stride 72)
        for (int idx = tid; idx < 8 * 14 * 72; idx += 256) {
            int cc  = idx / (14 * 72);
            int rem = idx - cc * (14 * 72);
            int r   = rem / 72;
            int col = rem - r * 72;
            int gr = h0 - 3 + r;
            int gc = col - 3;
            float v = 0.f;
            if ((unsigned)gr < 64u && (unsigned)gc < 64u)
                v = x[((size_t)(b * NC + c0 + cc) << 12) + (gr << 6) + gc];
            xs[idx] = v;
        }
        __syncthreads();

        #pragma unroll
        for (int cc = 0; cc < 8; cc++) {
            const float* basep = xs + cc * (14 * 72) + hloc * 72 + wloc;
            float ax = 0.f, ay = 0.f;
            #pragma unroll
            for (int i = 0; i < 7; i++) {
                const float2* rp = (const float2*)(basep + i * 72);
                float2 v0 = rp[0], v1 = rp[1], v2 = rp[2], v3 = rp[3];
                float xv0 = v0.x, xv1 = v0.y, xv2 = v1.x, xv3 = v1.y;
                float xv4 = v2.x, xv5 = v2.y, xv6 = v3.x, xv7 = v3.y;
                ax = fmaf(kv[i*7+0].x, xv0, ax);  ay = fmaf(kv[i*7+0].y, xv1, ay);
                ax = fmaf(kv[i*7+1].x, xv1, ax);  ay = fmaf(kv[i*7+1].y, xv2, ay);
                ax = fmaf(kv[i*7+2].x, xv2, ax);  ay = fmaf(kv[i*7+2].y, xv3, ay);
                ax = fmaf(kv[i*7+3].x, xv3, ax);  ay = fmaf(kv[i*7+3].y, xv4, ay);
                ax = fmaf(kv[i*7+4].x, xv4, ax);  ay = fmaf(kv[i*7+4].y, xv5, ay);
                ax = fmaf(kv[i*7+5].x, xv5, ax);  ay = fmaf(kv[i*7+5].y, xv6, ay);
                ax = fmaf(kv[i*7+6].x, xv6, ax);  ay = fmaf(kv[i*7+6].y, xv7, ay);
            }
            float2 res; res.x = ax; res.y = ay;
            *(float2*)(out + ((size_t)(b * NC + c0 + cc) << 12) + out_pix) = res;
        }
    }
}

extern "C" void kernel_launch(void* const* d_in, const int* in_sizes, int n_in,
                              void* d_out, int out_size)
{
    const float* x     = (const float*)d_in[0];
    const float* w1    = (const float*)d_in[1];
    const float* b1    = (const float*)d_in[2];
    const float* gamma = (const float*)d_in[3];
    const float* beta  = (const float*)d_in[4];
    const float* mean  = (const float*)d_in[5];
    const float* var   = (const float*)d_in[6];
    const float* w2    = (const float*)d_in[7];
    const float* b2    = (const float*)d_in[8];

    gen_kernel<<<128, 128>>>(x, w1, b1, gamma, beta, mean, var, w2, b2);
    inv_kernel<<<128, 256>>>(x, (float*)d_out);
}

// round 3
// speedup vs baseline: 1.7593x; 1.7593x over previous
#include <cuda_runtime.h>

#define HW   4096
#define NC   128
#define CR   32
#define KK   49

// scratch for generated per-pixel kernels: [B=4][49][64*64]
__device__ float g_kernel[4 * KK * HW];

// ---------------------------------------------------------------------------
// Kernel 1: generate involution kernels.
// 256 blocks x 256 threads. Block = 64 pixels, 4 "parts" per pixel.
// Stage 1: part p reduces channels [32p,32p+32) -> partial f[32] -> shared.
// Stage 2: every thread combines 4 partials + BN + ReLU -> f[32] in regs.
// Stage 3: part p computes kernel outputs t in [13p, 13p+13) (t<49) -> gmem.
// ---------------------------------------------------------------------------
__global__ __launch_bounds__(256) void gen_kernel(
    const float* __restrict__ x,  const float* __restrict__ w1,
    const float* __restrict__ b1, const float* __restrict__ gamma,
    const float* __restrict__ beta, const float* __restrict__ mean,
    const float* __restrict__ var,  const float* __restrict__ w2,
    const float* __restrict__ b2)
{
    __shared__ __align__(16) float w1t[NC * CR];    // [c][o]  16 KB
    __shared__ __align__(16) float w2tt[52 * CR];   // [t][o]  6.5 KB (pad t->52)
    __shared__ __align__(16) float fbuf[4 * CR * 64]; // [part][o][pix] 32 KB
    __shared__ float s_scale[CR], s_shift[CR];

    const int tid = threadIdx.x;

    for (int i = tid; i < NC * CR; i += 256) {
        int o = i >> 7, c = i & 127;
        w1t[c * CR + o] = w1[i];
    }
    for (int i = tid; i < 52 * CR; i += 256)
        w2tt[i] = (i < KK * CR) ? w2[i] : 0.f;
    if (tid < CR) {
        float sc = gamma[tid] * rsqrtf(var[tid] + 1e-5f);
        s_scale[tid] = sc;
        // fold conv bias b1 into the BN shift: (v+b1)*sc + (beta-mean*sc)
        s_shift[tid] = fmaf(b1[tid], sc, beta[tid] - mean[tid] * sc);
    }
    __syncthreads();

    const int pix_l = tid & 63;
    const int part  = tid >> 6;            // warp-uniform
    const int pixel = blockIdx.x * 64 + pix_l;
    const int b     = pixel >> 12;
    const int hw    = pixel & (HW - 1);

    // ---- stage 1: partial 1x1 conv over this part's 32 channels ----
    float fp[CR];
    #pragma unroll
    for (int o = 0; o < CR; o++) fp[o] = 0.f;

    const float* xp = x + ((size_t)(b * NC + part * 32)) * HW + hw;
    #pragma unroll 4
    for (int c = 0; c < 32; c++) {
        float xv = xp[(size_t)c * HW];
        const float4* wr = (const float4*)&w1t[(part * 32 + c) * CR];
        #pragma unroll
        for (int o4 = 0; o4 < 8; o4++) {
            float4 w = wr[o4];
            fp[o4*4+0] = fmaf(w.x, xv, fp[o4*4+0]);
            fp[o4*4+1] = fmaf(w.y, xv, fp[o4*4+1]);
            fp[o4*4+2] = fmaf(w.z, xv, fp[o4*4+2]);
            fp[o4*4+3] = fmaf(w.w, xv, fp[o4*4+3]);
        }
    }
    {
        float* fb = fbuf + part * (CR * 64) + pix_l;
        #pragma unroll
        for (int o = 0; o < CR; o++) fb[o * 64] = fp[o];
    }
    __syncthreads();

    // ---- stage 2: combine partials + BN + ReLU ----
    float f[CR];
    #pragma unroll
    for (int o = 0; o < CR; o++) {
        float v = fbuf[0*(CR*64) + o*64 + pix_l]
                + fbuf[1*(CR*64) + o*64 + pix_l]
                + fbuf[2*(CR*64) + o*64 + pix_l]
                + fbuf[3*(CR*64) + o*64 + pix_l];
        v = fmaf(v, s_scale[o], s_shift[o]);
        f[o] = fmaxf(v, 0.f);
    }

    // ---- stage 3: this part's 13 kernel outputs ----
    const int t0 = part * 13;
    float* kp = g_kernel + (size_t)b * KK * HW + hw;
    #pragma unroll
    for (int tt = 0; tt < 13; tt++) {
        int t = t0 + tt;
        const float4* wr = (const float4*)&w2tt[t * CR];
        float a0 = 0.f, a1 = 0.f, a2 = 0.f, a3 = 0.f;
        #pragma unroll
        for (int o4 = 0; o4 < 8; o4++) {
            float4 w = wr[o4];
            a0 = fmaf(w.x, f[o4*4+0], a0);
            a1 = fmaf(w.y, f[o4*4+1], a1);
            a2 = fmaf(w.z, f[o4*4+2], a2);
            a3 = fmaf(w.w, f[o4*4+3], a3);
        }
        if (t < KK)
            kp[(size_t)t * HW] = (a0 + a1) + (a2 + a3) + b2[t];
    }
}

// ---------------------------------------------------------------------------
// Kernel 2: involution accumulation.
// grid 512 = (b, 16 4-row tiles, 8 16-channel groups), 128 threads.
// warp = one 64-wide output row, thread = 2 adjacent pixels.
// 49 per-pixel kernel weights (float2) in registers, reused over 16 channels.
// Full 16-channel halo (10 rows x 72 cols, padded) staged once in shared.
// ---------------------------------------------------------------------------
__global__ __launch_bounds__(128) void inv_kernel(
    const float* __restrict__ x, float* __restrict__ out)
{
    __shared__ __align__(16) float xs[16 * 10 * 72];   // 46080 B

    const int bx = blockIdx.x;              // 0..511
    const int b  = bx >> 7;
    const int ht = (bx >> 3) & 15;          // 16 row-tiles of 4
    const int cg = bx & 7;                  // 8 groups of 16 channels
    const int h0 = ht * 4;
    const int c0 = cg * 16;

    const int tid  = threadIdx.x;
    const int hloc = tid >> 5;              // 0..3
    const int lane = tid & 31;
    const int wloc = lane * 2;

    // ---- halo load: 4 warps x 4 channels each, division-free ----
    {
        const int wid = hloc;               // warp id 0..3
        #pragma unroll
        for (int ch = 0; ch < 4; ch++) {
            const int cc = wid * 4 + ch;
            const float* xg = x + ((size_t)(b * NC + c0 + cc) << 12);
            float* xsc = xs + cc * (10 * 72);
            #pragma unroll
            for (int r = 0; r < 10; r++) {
                const int gr = h0 - 3 + r;
                const bool rok = (unsigned)gr < 64u;
                const float* xrow = xg + (gr << 6);
                #pragma unroll
                for (int s = 0; s < 3; s++) {
                    int col = lane + s * 32;
                    if (s < 2 || col < 72) {
                        int gc = col - 3;
                        float v = (rok && (unsigned)gc < 64u) ? xrow[gc] : 0.f;
                        xsc[r * 72 + col] = v;
                    }
                }
            }
        }
    }

    // ---- preload this thread's 49 kernel weights (2 pixels) ----
    float2 kv[KK];
    {
        const float* kp = g_kernel + (size_t)b * KK * HW + (h0 + hloc) * 64 + wloc;
        #pragma unroll
        for (int t = 0; t < KK; t++)
            kv[t] = *(const float2*)(kp + (size_t)t * HW);
    }
    __syncthreads();

    const size_t out_pix = (size_t)(h0 + hloc) * 64 + wloc;

    #pragma unroll
    for (int cc = 0; cc < 16; cc++) {
        const float* basep = xs + cc * (10 * 72) + hloc * 72 + wloc;
        float ax = 0.f, ay = 0.f;
        #pragma unroll
        for (int i = 0; i < 7; i++) {
            const float2* rp = (const float2*)(basep + i * 72);
            float2 v0 = rp[0], v1 = rp[1], v2 = rp[2], v3 = rp[3];
            ax = fmaf(kv[i*7+0].x, v0.x, ax);  ay = fmaf(kv[i*7+0].y, v0.y, ay);
            ax = fmaf(kv[i*7+1].x, v0.y, ax);  ay = fmaf(kv[i*7+1].y, v1.x, ay);
            ax = fmaf(kv[i*7+2].x, v1.x, ax);  ay = fmaf(kv[i*7+2].y, v1.y, ay);
            ax = fmaf(kv[i*7+3].x, v1.y, ax);  ay = fmaf(kv[i*7+3].y, v2.x, ay);
            ax = fmaf(kv[i*7+4].x, v2.x, ax);  ay = fmaf(kv[i*7+4].y, v2.y, ay);
            ax = fmaf(kv[i*7+5].x, v2.y, ax);  ay = fmaf(kv[i*7+5].y, v3.x, ay);
            ax = fmaf(kv[i*7+6].x, v3.x, ax);  ay = fmaf(kv[i*7+6].y, v3.y, ay);
        }
        float2 res; res.x = ax; res.y = ay;
        *(float2*)(out + ((size_t)(b * NC + c0 + cc) << 12) + out_pix) = res;
    }
}

extern "C" void kernel_launch(void* const* d_in, const int* in_sizes, int n_in,
                              void* d_out, int out_size)
{
    const float* x     = (const float*)d_in[0];
    const float* w1    = (const float*)d_in[1];
    const float* b1    = (const float*)d_in[2];
    const float* gamma = (const float*)d_in[3];
    const float* beta  = (const float*)d_in[4];
    const float* mean  = (const float*)d_in[5];
    const float* var   = (const float*)d_in[6];
    const float* w2    = (const float*)d_in[7];
    const float* b2    = (const float*)d_in[8];

    gen_kernel<<<256, 256>>>(x, w1, b1, gamma, beta, mean, var, w2, b2);
    inv_kernel<<<512, 128>>>(x, (float*)d_out);
}